// round 13
// baseline (speedup 1.0000x reference)
#include <cuda_runtime.h>
#include <cstdint>

typedef unsigned long long ull;

#define NMAX   100000
#define EMAX   2000000
#define F_IN   500
#define H1     64
#define C_OUT  40
#define BM     256            // rows per CTA tile (16 warps x 16 rows)
#define GW     16             // warps
#define GT     512            // threads
#define KC     32             // k per chunk
#define NCHUNK 16             // 16*32 = 512 >= 500 (zero-padded)
#define WHROWS 256            // W rows resident per half
#define XDEPTH 4              // x pipeline depth (buffers per warp)
#define XSTR   36             // x smem row stride (floats): bank 4*tr+tc, conflict-free
#define WSTR   68             // W smem row stride (floats): bank 4*tc+tr, conflict-free
#define NBMAX  128

// Scratch (allocation-free rule: __device__ globals)
__device__ int   g_degi[NMAX];
__device__ float g_dinv[NMAX];
__device__ float g_h1  [(size_t)NMAX * H1];
__device__ float g_t2  [(size_t)NMAX * C_OUT];
__device__ int   g_src [EMAX];
__device__ int   g_dst [EMAX];
__device__ int   g_adj [EMAX];
__device__ int   g_row [NMAX + 1];
__device__ int   g_cur [NMAX];
__device__ int   g_bsum[NBMAX];
__device__ int   g_boff[NBMAX];
__device__ int   g_is64;

// ---------- helpers ----------
__device__ __forceinline__ float to_tf32(float f) {
    float r;
    asm("cvt.rna.tf32.f32 %0, %1;" : "=f"(r) : "f"(f));
    return r;
}
__device__ __forceinline__ void mma_tf32(
    float& d0, float& d1, float& d2, float& d3,
    uint32_t a0, uint32_t a1, uint32_t a2, uint32_t a3,
    uint32_t b0, uint32_t b1) {
    asm volatile(
        "mma.sync.aligned.m16n8k8.row.col.f32.tf32.tf32.f32 "
        "{%0,%1,%2,%3}, {%4,%5,%6,%7}, {%8,%9}, {%0,%1,%2,%3};"
        : "+f"(d0), "+f"(d1), "+f"(d2), "+f"(d3)
        : "r"(a0), "r"(a1), "r"(a2), "r"(a3), "r"(b0), "r"(b1));
}
__device__ __forceinline__ uint32_t smem_u32(const void* p) {
    return (uint32_t)__cvta_generic_to_shared(p);
}
__device__ __forceinline__ void cp16(uint32_t dst, const void* src, int srcsize) {
    asm volatile("cp.async.cg.shared.global [%0], [%1], 16, %2;"
                 :: "r"(dst), "l"(src), "r"(srcsize) : "memory");
}

// ---------- edge dtype detection ----------
__global__ void k_detect(const void* __restrict__ ei, int E, int n) {
    const long long* p = (const long long*)ei;
    int m = min(4096, E);
    int bad = 0;
    for (int i = threadIdx.x; i < m; i += blockDim.x) {
        long long v = p[i];
        if (v < 0 || v >= (long long)n) bad = 1;
    }
    bad = __syncthreads_or(bad);
    if (threadIdx.x == 0) g_is64 = bad ? 0 : 1;
}

__global__ void k_zero(int n) {
    int i = blockIdx.x * blockDim.x + threadIdx.x;
    if (i < n) g_degi[i] = 0;
}

// ---------- fused: edge int32 conversion + degree histogram ----------
__global__ void k_convert_hist(const void* __restrict__ ei, int E) {
    int i = blockIdx.x * blockDim.x + threadIdx.x;
    if (i >= E) return;
    int s, d;
    if (g_is64) {
        const long long* p = (const long long*)ei;
        s = (int)p[i];
        d = (int)p[E + i];
    } else {
        const int* p = (const int*)ei;
        s = p[i];
        d = p[E + i];
    }
    g_src[i] = s;
    g_dst[i] = d;
    atomicAdd(&g_degi[d], 1);
}

// ---------- GEMM1 (launch #4 -> profiled): h1 = dinv * (x @ W1) ----------
// mma.sync.m16n8k8.tf32. W resident in smem in 2 halves (256 k-rows each);
// x per-warp 4-deep pipelined via cp.async (wait_group 2) -> ~3 chunks of
// x in flight per warp. One CTA barrier at W half swap (chunk 8).
__global__ void __launch_bounds__(GT)
k_gemm1(const float* __restrict__ x, const float* __restrict__ W, int n) {
    extern __shared__ float sm[];
    float* ws = sm;                              // [WHROWS][WSTR]
    float* xs = sm + WHROWS * WSTR;              // [GW][XDEPTH][16][XSTR]

    const int tid  = threadIdx.x;
    const int lane = tid & 31;
    const int w    = tid >> 5;                   // 0..15
    const int tr   = lane >> 2;                  // 0..7
    const int tc   = lane & 3;                   // 0..3
    const int row0 = blockIdx.x * BM;
    const int wr   = w * 16;                     // warp's first local row

    float* xw = xs + w * (XDEPTH * 16 * XSTR);   // this warp's buffers
    const uint32_t xw_u32 = smem_u32(xw);

    // per-lane cp.async geometry: 2 lanes per row, 4 x 16B each
    const int lrow  = lane >> 1;                 // 0..15 local row
    const int lhalf = lane & 1;                  // 0/1 -> float4 group
    const int grow  = row0 + wr + lrow;
    const bool rok  = (grow < n);
    const float* gbase = x + (size_t)(rok ? grow : 0) * F_IN;

    #define ISSUE(cc, bb)                                                       \
    {                                                                           \
        _Pragma("unroll")                                                       \
        for (int q = 0; q < 4; q++) {                                           \
            const int f4 = lhalf * 4 + q;                                       \
            const int kg = (cc) * KC + f4 * 4;                                  \
            const int ok = (rok && (kg + 4 <= F_IN)) ? 16 : 0;                  \
            const uint32_t dst = xw_u32 +                                       \
                (uint32_t)(((bb) * 16 + lrow) * XSTR + f4 * 4) * 4u;            \
            cp16(dst, gbase + kg, ok);                                          \
        }                                                                       \
        asm volatile("cp.async.commit_group;" ::: "memory");                    \
    }

    // prologue: 3 chunks in flight before W staging
    ISSUE(0, 0)
    ISSUE(1, 1)
    ISSUE(2, 2)

    // stage W half 0 (k rows 0..255), tf32-rounded
    const float4* __restrict__ W4 = (const float4*)W;
    #pragma unroll 1
    for (int i = tid; i < WHROWS * (H1 / 4); i += GT) {
        const int k = i >> 4, q = i & 15;
        float4 v = make_float4(0.f, 0.f, 0.f, 0.f);
        if (k < F_IN) v = W4[(size_t)k * (H1 / 4) + q];
        v.x = to_tf32(v.x); v.y = to_tf32(v.y);
        v.z = to_tf32(v.z); v.w = to_tf32(v.w);
        *(float4*)&ws[k * WSTR + 4 * q] = v;
    }
    __syncthreads();

    float d[8][4];
    #pragma unroll
    for (int j = 0; j < 8; j++)
        #pragma unroll
        for (int q = 0; q < 4; q++) d[j][q] = 0.0f;

    for (int c = 0; c < NCHUNK; c++) {
        if (c == 8) {
            // swap in W half 1 (k rows 256..511, zero-padded past 500)
            __syncthreads();
            #pragma unroll 1
            for (int i = tid; i < WHROWS * (H1 / 4); i += GT) {
                const int kl = i >> 4, q = i & 15;
                const int k = WHROWS + kl;
                float4 v = make_float4(0.f, 0.f, 0.f, 0.f);
                if (k < F_IN) v = W4[(size_t)k * (H1 / 4) + q];
                v.x = to_tf32(v.x); v.y = to_tf32(v.y);
                v.z = to_tf32(v.z); v.w = to_tf32(v.w);
                *(float4*)&ws[kl * WSTR + 4 * q] = v;
            }
            __syncthreads();
        }

        asm volatile("cp.async.wait_group 2;" ::: "memory");
        __syncwarp();

        const float* xb = xw + (c & 3) * (16 * XSTR);
        const uint32_t* xa_lo = (const uint32_t*)(xb + tr * XSTR + tc);
        const uint32_t* xa_hi = (const uint32_t*)(xb + (tr + 8) * XSTR + tc);
        const int wloc = (c & 7) * KC;
        const uint32_t* wb0 = (const uint32_t*)(ws + (wloc + tc) * WSTR + tr);
        const uint32_t* wb1 = (const uint32_t*)(ws + (wloc + tc + 4) * WSTR + tr);

        #pragma unroll
        for (int s = 0; s < KC / 8; s++) {
            const int kk = 8 * s;
            const uint32_t a0 = xa_lo[kk];
            const uint32_t a1 = xa_hi[kk];
            const uint32_t a2 = xa_lo[kk + 4];
            const uint32_t a3 = xa_hi[kk + 4];
            #pragma unroll
            for (int j = 0; j < 8; j++) {
                const uint32_t b0 = wb0[kk * WSTR + 8 * j];
                const uint32_t b1 = wb1[kk * WSTR + 8 * j];
                mma_tf32(d[j][0], d[j][1], d[j][2], d[j][3], a0, a1, a2, a3, b0, b1);
            }
        }

        if (c + 3 < NCHUNK) {
            ISSUE(c + 3, (c + 3) & 3)
        } else {
            asm volatile("cp.async.commit_group;" ::: "memory");  // empty group
        }
    }
    #undef ISSUE

    // ---- epilogue: dinv scale + store (fragment mapping verified R11/R12) ----
    const int r_lo = row0 + wr + tr;
    const int r_hi = r_lo + 8;
    if (r_lo < n) {
        const float dd = rsqrtf((float)g_degi[r_lo] + 1.0f);
        if (tc == 0) g_dinv[r_lo] = dd;
        #pragma unroll
        for (int j = 0; j < 8; j++) {
            float2 v = make_float2(dd * d[j][0], dd * d[j][1]);
            *(float2*)&g_h1[(size_t)r_lo * H1 + 8 * j + 2 * tc] = v;
        }
    }
    if (r_hi < n) {
        const float dd = rsqrtf((float)g_degi[r_hi] + 1.0f);
        if (tc == 0) g_dinv[r_hi] = dd;
        #pragma unroll
        for (int j = 0; j < 8; j++) {
            float2 v = make_float2(dd * d[j][2], dd * d[j][3]);
            *(float2*)&g_h1[(size_t)r_hi * H1 + 8 * j + 2 * tc] = v;
        }
    }
}

// ---------- CSR build: block scan over degrees ----------
__global__ void __launch_bounds__(1024)
k_scanA(int n) {
    __shared__ int s0[1024], s1[1024];
    const int tid = threadIdx.x;
    const int i = blockIdx.x * 1024 + tid;
    int v = (i < n) ? g_degi[i] : 0;
    s0[tid] = v;
    __syncthreads();
    int* a = s0; int* b = s1;
    #pragma unroll
    for (int off = 1; off < 1024; off <<= 1) {
        b[tid] = a[tid] + ((tid >= off) ? a[tid - off] : 0);
        __syncthreads();
        int* t = a; a = b; b = t;
    }
    if (i < n) g_row[i] = a[tid] - v;
    if (tid == 1023) g_bsum[blockIdx.x] = a[1023];
}
__global__ void __launch_bounds__(NBMAX)
k_scanB(int nb) {
    __shared__ int s0[NBMAX], s1[NBMAX];
    const int tid = threadIdx.x;
    int v = (tid < nb) ? g_bsum[tid] : 0;
    s0[tid] = v;
    __syncthreads();
    int* a = s0; int* b = s1;
    #pragma unroll
    for (int off = 1; off < NBMAX; off <<= 1) {
        b[tid] = a[tid] + ((tid >= off) ? a[tid - off] : 0);
        __syncthreads();
        int* t = a; a = b; b = t;
    }
    if (tid < nb) g_boff[tid] = a[tid] - v;
}
__global__ void k_scanC(int n, int E) {
    int i = blockIdx.x * blockDim.x + threadIdx.x;
    if (i < n) {
        int r = g_row[i] + g_boff[i >> 10];
        g_row[i] = r;
        g_cur[i] = r;
    }
    if (i == 0) g_row[n] = E;
}
__global__ void k_fill(int E) {
    int e = blockIdx.x * blockDim.x + threadIdx.x;
    if (e >= E) return;
    int pos = atomicAdd(&g_cur[g_dst[e]], 1);
    g_adj[pos] = g_src[e];
}

// ---------- fused layer-1 aggregate + bias + relu + GEMM2: warp per node ----------
__global__ void __launch_bounds__(256)
k_l1(const float* __restrict__ b1, const float* __restrict__ W2, int n) {
    __shared__ float W2s[H1 * C_OUT];
    __shared__ float b1s[H1];
    const int tid = threadIdx.x;
    for (int i = tid; i < H1 * C_OUT; i += 256) W2s[i] = W2[i];
    if (tid < H1) b1s[tid] = b1[tid];
    __syncthreads();

    const int lane = tid & 31;
    const int d = blockIdx.x * 8 + (tid >> 5);
    if (d >= n) return;

    const int beg = g_row[d];
    const int end = g_row[d + 1];
    const float2* __restrict__ h2 = (const float2*)g_h1;

    float2 a0 = h2[(size_t)d * 32 + lane];   // self-loop
    float2 a1 = make_float2(0.f, 0.f);
    float2 a2 = make_float2(0.f, 0.f);
    float2 a3 = make_float2(0.f, 0.f);

    int i = beg;
    for (; i + 16 <= end; i += 16) {
        int s[16];
        #pragma unroll
        for (int j = 0; j < 16; j++) s[j] = g_adj[i + j];
        float2 v[16];
        #pragma unroll
        for (int j = 0; j < 16; j++) v[j] = h2[(size_t)s[j] * 32 + lane];
        #pragma unroll
        for (int j = 0; j < 16; j += 4) {
            a0.x += v[j].x;     a0.y += v[j].y;
            a1.x += v[j + 1].x; a1.y += v[j + 1].y;
            a2.x += v[j + 2].x; a2.y += v[j + 2].y;
            a3.x += v[j + 3].x; a3.y += v[j + 3].y;
        }
    }
    for (; i + 4 <= end; i += 4) {
        int s[4];
        #pragma unroll
        for (int j = 0; j < 4; j++) s[j] = g_adj[i + j];
        float2 v[4];
        #pragma unroll
        for (int j = 0; j < 4; j++) v[j] = h2[(size_t)s[j] * 32 + lane];
        a0.x += v[0].x; a0.y += v[0].y;  a1.x += v[1].x; a1.y += v[1].y;
        a2.x += v[2].x; a2.y += v[2].y;  a3.x += v[3].x; a3.y += v[3].y;
    }
    for (; i < end; i++) {
        float2 v = h2[(size_t)g_adj[i] * 32 + lane];
        a0.x += v.x; a0.y += v.y;
    }
    a0.x += a1.x + a2.x + a3.x;
    a0.y += a1.y + a2.y + a3.y;

    const float dd = g_dinv[d];
    const float hx = fmaxf(a0.x * dd + b1s[2 * lane],     0.0f);
    const float hy = fmaxf(a0.y * dd + b1s[2 * lane + 1], 0.0f);

    float c0 = 0.0f, c1 = 0.0f;
    #pragma unroll
    for (int k2 = 0; k2 < 32; k2++) {
        const float ha = __shfl_sync(0xffffffffu, hx, k2);
        const float hb = __shfl_sync(0xffffffffu, hy, k2);
        c0 += ha * W2s[(2 * k2)     * C_OUT + lane];
        c0 += hb * W2s[(2 * k2 + 1) * C_OUT + lane];
        if (lane < 8) {
            c1 += ha * W2s[(2 * k2)     * C_OUT + 32 + lane];
            c1 += hb * W2s[(2 * k2 + 1) * C_OUT + 32 + lane];
        }
    }
    g_t2[(size_t)d * C_OUT + lane] = c0 * dd;
    if (lane < 8) g_t2[(size_t)d * C_OUT + 32 + lane] = c1 * dd;
}

// ---------- fused layer-2 aggregate + bias + relu + log_softmax: warp per node ----------
__global__ void __launch_bounds__(256)
k_l2(float* __restrict__ out, const float* __restrict__ b2, int n) {
    __shared__ float b2s[C_OUT];
    const int tid = threadIdx.x;
    if (tid < C_OUT) b2s[tid] = b2[tid];
    __syncthreads();

    const int lane = tid & 31;
    const int d = blockIdx.x * 8 + (tid >> 5);
    if (d >= n) return;

    const int beg = g_row[d];
    const int end = g_row[d + 1];
    const bool lo8 = (lane < 8);

    float aa0 = g_t2[(size_t)d * C_OUT + lane];
    float ab0 = lo8 ? g_t2[(size_t)d * C_OUT + 32 + lane] : 0.0f;
    float aa1 = 0.f, ab1 = 0.f, aa2 = 0.f, ab2 = 0.f, aa3 = 0.f, ab3 = 0.f;

    int i = beg;
    for (; i + 16 <= end; i += 16) {
        int s[16];
        #pragma unroll
        for (int j = 0; j < 16; j++) s[j] = g_adj[i + j];
        float va[16];
        #pragma unroll
        for (int j = 0; j < 16; j++) va[j] = g_t2[(size_t)s[j] * C_OUT + lane];
        #pragma unroll
        for (int j = 0; j < 16; j += 4) {
            aa0 += va[j]; aa1 += va[j + 1]; aa2 += va[j + 2]; aa3 += va[j + 3];
        }
        if (lo8) {
            float vb[16];
            #pragma unroll
            for (int j = 0; j < 16; j++) vb[j] = g_t2[(size_t)s[j] * C_OUT + 32 + lane];
            #pragma unroll
            for (int j = 0; j < 16; j += 4) {
                ab0 += vb[j]; ab1 += vb[j + 1]; ab2 += vb[j + 2]; ab3 += vb[j + 3];
            }
        }
    }
    for (; i + 4 <= end; i += 4) {
        int s[4];
        #pragma unroll
        for (int j = 0; j < 4; j++) s[j] = g_adj[i + j];
        aa0 += g_t2[(size_t)s[0] * C_OUT + lane];
        aa1 += g_t2[(size_t)s[1] * C_OUT + lane];
        aa2 += g_t2[(size_t)s[2] * C_OUT + lane];
        aa3 += g_t2[(size_t)s[3] * C_OUT + lane];
        if (lo8) {
            ab0 += g_t2[(size_t)s[0] * C_OUT + 32 + lane];
            ab1 += g_t2[(size_t)s[1] * C_OUT + 32 + lane];
            ab2 += g_t2[(size_t)s[2] * C_OUT + 32 + lane];
            ab3 += g_t2[(size_t)s[3] * C_OUT + 32 + lane];
        }
    }
    for (; i < end; i++) {
        int s = g_adj[i];
        aa0 += g_t2[(size_t)s * C_OUT + lane];
        if (lo8) ab0 += g_t2[(size_t)s * C_OUT + 32 + lane];
    }
    aa0 += aa1 + aa2 + aa3;
    ab0 += ab1 + ab2 + ab3;

    const float dd = g_dinv[d];
    const float v0 = fmaxf(aa0 * dd + b2s[lane], 0.0f);
    const float v1 = lo8 ? fmaxf(ab0 * dd + b2s[32 + lane], 0.0f) : -1e30f;

    float m = fmaxf(v0, v1);
    #pragma unroll
    for (int o = 16; o; o >>= 1) m = fmaxf(m, __shfl_xor_sync(0xffffffffu, m, o));
    float s = expf(v0 - m) + (lo8 ? expf(v1 - m) : 0.0f);
    #pragma unroll
    for (int o = 16; o; o >>= 1) s += __shfl_xor_sync(0xffffffffu, s, o);
    const float lse = m + logf(s);

    out[(size_t)d * C_OUT + lane] = v0 - lse;
    if (lo8) out[(size_t)d * C_OUT + 32 + lane] = v1 - lse;
}

extern "C" void kernel_launch(void* const* d_in, const int* in_sizes, int n_in,
                              void* d_out, int out_size) {
    const float* x  = (const float*)d_in[0];
    const void*  ei = d_in[1];
    const float* W1 = (const float*)d_in[2];
    const float* b1 = (const float*)d_in[3];
    const float* W2 = (const float*)d_in[4];
    const float* b2 = (const float*)d_in[5];
    float*       out = (float*)d_out;

    const int n = in_sizes[0] / F_IN;
    const int E = in_sizes[1] / 2;
    const int nb = (n + 1023) / 1024;

    k_detect      <<<1, 256>>>(ei, E, n);                 // launch 1
    k_zero        <<<(n + 255) / 256, 256>>>(n);          // launch 2
    k_convert_hist<<<(E + 255) / 256, 256>>>(ei, E);      // launch 3

    const int smem = (WHROWS * WSTR + GW * XDEPTH * 16 * XSTR) * (int)sizeof(float); // 217088 B
    cudaFuncSetAttribute(k_gemm1, cudaFuncAttributeMaxDynamicSharedMemorySize, smem);
    k_gemm1<<<(n + BM - 1) / BM, GT, smem>>>(x, W1, n);   // launch 4 (profiled)

    k_scanA <<<nb, 1024>>>(n);
    k_scanB <<<1, NBMAX>>>(nb);
    k_scanC <<<(n + 255) / 256, 256>>>(n, E);
    k_fill  <<<(E + 255) / 256, 256>>>(E);

    k_l1<<<(n + 7) / 8, 256>>>(b1, W2, n);
    k_l2<<<(n + 7) / 8, 256>>>(out, b2, n);
}

// round 14
// speedup vs baseline: 1.1311x; 1.1311x over previous
#include <cuda_runtime.h>
#include <cuda_bf16.h>
#include <cstdint>

typedef unsigned long long ull;

#define NMAX   100000
#define EMAX   2000000
#define F_IN   500
#define H1     64
#define C_OUT  40
#define BM     256            // rows per CTA tile (16 warps x 16 rows)
#define GW     16             // warps
#define GT     512            // threads
#define KC     32             // k per chunk
#define NCHUNK 16             // 16*32 = 512 >= 500 (zero-padded)
#define WROWS  512
#define XSTR   36             // x smem row stride (floats)
#define WSTR   72             // W smem row stride (floats)
#define NBMAX  128

// Scratch (allocation-free rule: __device__ globals)
__device__ int      g_degi[NMAX];
__device__ float    g_dinv[NMAX];
__device__ uint32_t g_h1 [(size_t)NMAX * 32];   // bf16x2: cols {2j,2j+1} in word j
__device__ uint32_t g_t2 [(size_t)NMAX * 20];   // bf16x2: cols {2j,2j+1} in word j
__device__ int      g_src [EMAX];
__device__ int      g_dst [EMAX];
__device__ int      g_adj [EMAX];
__device__ int      g_row [NMAX + 1];
__device__ int      g_cur [NMAX];
__device__ int      g_bsum[NBMAX];
__device__ int      g_boff[NBMAX];
__device__ int      g_is64;

// ---------- helpers ----------
__device__ __forceinline__ float to_tf32(float f) {
    float r;
    asm("cvt.rna.tf32.f32 %0, %1;" : "=f"(r) : "f"(f));
    return r;
}
__device__ __forceinline__ void mma_tf32(
    float& d0, float& d1, float& d2, float& d3,
    uint32_t a0, uint32_t a1, uint32_t a2, uint32_t a3,
    uint32_t b0, uint32_t b1) {
    asm volatile(
        "mma.sync.aligned.m16n8k8.row.col.f32.tf32.tf32.f32 "
        "{%0,%1,%2,%3}, {%4,%5,%6,%7}, {%8,%9}, {%0,%1,%2,%3};"
        : "+f"(d0), "+f"(d1), "+f"(d2), "+f"(d3)
        : "r"(a0), "r"(a1), "r"(a2), "r"(a3), "r"(b0), "r"(b1));
}
__device__ __forceinline__ uint32_t smem_u32(const void* p) {
    return (uint32_t)__cvta_generic_to_shared(p);
}
__device__ __forceinline__ void cp16(uint32_t dst, const void* src, int srcsize) {
    asm volatile("cp.async.cg.shared.global [%0], [%1], 16, %2;"
                 :: "r"(dst), "l"(src), "r"(srcsize) : "memory");
}
__device__ __forceinline__ uint32_t packbf(float lo, float hi) {
    __nv_bfloat162 h = __floats2bfloat162_rn(lo, hi);   // .x = lo (low 16 bits)
    return *(uint32_t*)&h;
}
__device__ __forceinline__ float bflo(uint32_t u) { return __uint_as_float(u << 16); }
__device__ __forceinline__ float bfhi(uint32_t u) { return __uint_as_float(u & 0xFFFF0000u); }

// ---------- edge dtype detection ----------
__global__ void k_detect(const void* __restrict__ ei, int E, int n) {
    const long long* p = (const long long*)ei;
    int m = min(4096, E);
    int bad = 0;
    for (int i = threadIdx.x; i < m; i += blockDim.x) {
        long long v = p[i];
        if (v < 0 || v >= (long long)n) bad = 1;
    }
    bad = __syncthreads_or(bad);
    if (threadIdx.x == 0) g_is64 = bad ? 0 : 1;
}

__global__ void k_zero(int n) {
    int i = blockIdx.x * blockDim.x + threadIdx.x;
    if (i < n) g_degi[i] = 0;
}

// ---------- fused: edge int32 conversion + degree histogram ----------
__global__ void k_convert_hist(const void* __restrict__ ei, int E) {
    int i = blockIdx.x * blockDim.x + threadIdx.x;
    if (i >= E) return;
    int s, d;
    if (g_is64) {
        const long long* p = (const long long*)ei;
        s = (int)p[i];
        d = (int)p[E + i];
    } else {
        const int* p = (const int*)ei;
        s = p[i];
        d = p[E + i];
    }
    g_src[i] = s;
    g_dst[i] = d;
    atomicAdd(&g_degi[d], 1);
}

// ---------- GEMM1 (launch #4 -> profiled): h1 = bf16( dinv * (x @ W1) ) ----------
// R12 structure verbatim: W resident (one barrier), per-warp 2-deep cp.async.
__global__ void __launch_bounds__(GT)
k_gemm1(const float* __restrict__ x, const float* __restrict__ W, int n) {
    extern __shared__ float sm[];
    float* ws = sm;                         // [512][WSTR]
    float* xs = sm + WROWS * WSTR;          // [GW][2][16][XSTR]

    const int tid  = threadIdx.x;
    const int lane = tid & 31;
    const int w    = tid >> 5;
    const int tr   = lane >> 2;
    const int tc   = lane & 3;
    const int row0 = blockIdx.x * BM;
    const int wr   = w * 16;

    float* xw = xs + w * (2 * 16 * XSTR);
    const uint32_t xw_u32 = smem_u32(xw);

    const int lrow  = lane >> 1;
    const int lhalf = lane & 1;
    const int grow  = row0 + wr + lrow;
    const bool rok  = (grow < n);
    const float* gbase = x + (size_t)(rok ? grow : 0) * F_IN;

    #define ISSUE(cc, bb)                                                       \
    {                                                                           \
        _Pragma("unroll")                                                       \
        for (int q = 0; q < 4; q++) {                                           \
            const int f4 = lhalf * 4 + q;                                       \
            const int kg = (cc) * KC + f4 * 4;                                  \
            const int ok = (rok && (kg + 4 <= F_IN)) ? 16 : 0;                  \
            const uint32_t dst = xw_u32 +                                       \
                (uint32_t)(((bb) * 16 + lrow) * XSTR + f4 * 4) * 4u;            \
            cp16(dst, gbase + kg, ok);                                          \
        }                                                                       \
        asm volatile("cp.async.commit_group;" ::: "memory");                    \
    }

    ISSUE(0, 0)
    ISSUE(1, 1)

    const float4* __restrict__ W4 = (const float4*)W;
    #pragma unroll 1
    for (int i = tid; i < WROWS * (H1 / 4); i += GT) {
        const int k = i >> 4, q = i & 15;
        float4 v = make_float4(0.f, 0.f, 0.f, 0.f);
        if (k < F_IN) v = W4[(size_t)k * (H1 / 4) + q];
        v.x = to_tf32(v.x); v.y = to_tf32(v.y);
        v.z = to_tf32(v.z); v.w = to_tf32(v.w);
        *(float4*)&ws[k * WSTR + 4 * q] = v;
    }
    __syncthreads();   // only CTA barrier

    float d[8][4];
    #pragma unroll
    for (int j = 0; j < 8; j++)
        #pragma unroll
        for (int q = 0; q < 4; q++) d[j][q] = 0.0f;

    for (int c = 0; c < NCHUNK; c++) {
        asm volatile("cp.async.wait_group 1;" ::: "memory");
        __syncwarp();

        const int buf = c & 1;
        const float* xb = xw + buf * (16 * XSTR);
        const uint32_t* xa_lo = (const uint32_t*)(xb + tr * XSTR + tc);
        const uint32_t* xa_hi = (const uint32_t*)(xb + (tr + 8) * XSTR + tc);
        const uint32_t* wb0 = (const uint32_t*)(ws + (c * KC + tc) * WSTR + tr);
        const uint32_t* wb1 = (const uint32_t*)(ws + (c * KC + tc + 4) * WSTR + tr);

        #pragma unroll
        for (int s = 0; s < KC / 8; s++) {
            const int kk = 8 * s;
            const uint32_t a0 = xa_lo[kk];
            const uint32_t a1 = xa_hi[kk];
            const uint32_t a2 = xa_lo[kk + 4];
            const uint32_t a3 = xa_hi[kk + 4];
            #pragma unroll
            for (int j = 0; j < 8; j++) {
                const uint32_t b0 = wb0[kk * WSTR + 8 * j];
                const uint32_t b1 = wb1[kk * WSTR + 8 * j];
                mma_tf32(d[j][0], d[j][1], d[j][2], d[j][3], a0, a1, a2, a3, b0, b1);
            }
        }

        if (c + 2 < NCHUNK) {
            ISSUE(c + 2, buf)
        } else {
            asm volatile("cp.async.commit_group;" ::: "memory");
        }
    }
    #undef ISSUE

    // ---- epilogue: dinv scale + bf16 pack + store ----
    const int r_lo = row0 + wr + tr;
    const int r_hi = r_lo + 8;
    if (r_lo < n) {
        const float dd = rsqrtf((float)g_degi[r_lo] + 1.0f);
        if (tc == 0) g_dinv[r_lo] = dd;
        #pragma unroll
        for (int j = 0; j < 8; j++)   // cols 8j+2tc, 8j+2tc+1 -> word 4j+tc
            g_h1[(size_t)r_lo * 32 + 4 * j + tc] = packbf(dd * d[j][0], dd * d[j][1]);
    }
    if (r_hi < n) {
        const float dd = rsqrtf((float)g_degi[r_hi] + 1.0f);
        if (tc == 0) g_dinv[r_hi] = dd;
        #pragma unroll
        for (int j = 0; j < 8; j++)
            g_h1[(size_t)r_hi * 32 + 4 * j + tc] = packbf(dd * d[j][2], dd * d[j][3]);
    }
}

// ---------- CSR build: block scan over degrees ----------
__global__ void __launch_bounds__(1024)
k_scanA(int n) {
    __shared__ int s0[1024], s1[1024];
    const int tid = threadIdx.x;
    const int i = blockIdx.x * 1024 + tid;
    int v = (i < n) ? g_degi[i] : 0;
    s0[tid] = v;
    __syncthreads();
    int* a = s0; int* b = s1;
    #pragma unroll
    for (int off = 1; off < 1024; off <<= 1) {
        b[tid] = a[tid] + ((tid >= off) ? a[tid - off] : 0);
        __syncthreads();
        int* t = a; a = b; b = t;
    }
    if (i < n) g_row[i] = a[tid] - v;
    if (tid == 1023) g_bsum[blockIdx.x] = a[1023];
}
__global__ void __launch_bounds__(NBMAX)
k_scanB(int nb) {
    __shared__ int s0[NBMAX], s1[NBMAX];
    const int tid = threadIdx.x;
    int v = (tid < nb) ? g_bsum[tid] : 0;
    s0[tid] = v;
    __syncthreads();
    int* a = s0; int* b = s1;
    #pragma unroll
    for (int off = 1; off < NBMAX; off <<= 1) {
        b[tid] = a[tid] + ((tid >= off) ? a[tid - off] : 0);
        __syncthreads();
        int* t = a; a = b; b = t;
    }
    if (tid < nb) g_boff[tid] = a[tid] - v;
}
__global__ void k_scanC(int n, int E) {
    int i = blockIdx.x * blockDim.x + threadIdx.x;
    if (i < n) {
        int r = g_row[i] + g_boff[i >> 10];
        g_row[i] = r;
        g_cur[i] = r;
    }
    if (i == 0) g_row[n] = E;
}
__global__ void k_fill(int E) {
    int e = blockIdx.x * blockDim.x + threadIdx.x;
    if (e >= E) return;
    int pos = atomicAdd(&g_cur[g_dst[e]], 1);
    g_adj[pos] = g_src[e];
}

// ---------- fused layer-1 aggregate + bias + relu + GEMM2: warp per node ----------
__global__ void __launch_bounds__(256)
k_l1(const float* __restrict__ b1, const float* __restrict__ W2, int n) {
    __shared__ float W2s[H1 * C_OUT];
    __shared__ float b1s[H1];
    const int tid = threadIdx.x;
    for (int i = tid; i < H1 * C_OUT; i += 256) W2s[i] = W2[i];
    if (tid < H1) b1s[tid] = b1[tid];
    __syncthreads();

    const int lane = tid & 31;
    const int d = blockIdx.x * 8 + (tid >> 5);
    if (d >= n) return;

    const int beg = g_row[d];
    const int end = g_row[d + 1];

    // self-loop term (bf16x2 word = cols {2*lane, 2*lane+1})
    uint32_t su = g_h1[(size_t)d * 32 + lane];
    float ax0 = bflo(su), ay0 = bfhi(su);
    float ax1 = 0.f, ay1 = 0.f, ax2 = 0.f, ay2 = 0.f, ax3 = 0.f, ay3 = 0.f;

    int i = beg;
    for (; i + 8 <= end; i += 8) {
        int s[8];
        #pragma unroll
        for (int j = 0; j < 8; j++) s[j] = g_adj[i + j];
        uint32_t u[8];
        #pragma unroll
        for (int j = 0; j < 8; j++) u[j] = g_h1[(size_t)s[j] * 32 + lane];
        ax0 += bflo(u[0]); ay0 += bfhi(u[0]);  ax1 += bflo(u[1]); ay1 += bfhi(u[1]);
        ax2 += bflo(u[2]); ay2 += bfhi(u[2]);  ax3 += bflo(u[3]); ay3 += bfhi(u[3]);
        ax0 += bflo(u[4]); ay0 += bfhi(u[4]);  ax1 += bflo(u[5]); ay1 += bfhi(u[5]);
        ax2 += bflo(u[6]); ay2 += bfhi(u[6]);  ax3 += bflo(u[7]); ay3 += bfhi(u[7]);
    }
    for (; i < end; i++) {
        uint32_t u = g_h1[(size_t)g_adj[i] * 32 + lane];
        ax0 += bflo(u); ay0 += bfhi(u);
    }
    ax0 += ax1 + ax2 + ax3;
    ay0 += ay1 + ay2 + ay3;

    const float dd = g_dinv[d];
    const float hx = fmaxf(ax0 * dd + b1s[2 * lane],     0.0f);
    const float hy = fmaxf(ay0 * dd + b1s[2 * lane + 1], 0.0f);

    float c0 = 0.0f, c1 = 0.0f;
    #pragma unroll
    for (int k2 = 0; k2 < 32; k2++) {
        const float ha = __shfl_sync(0xffffffffu, hx, k2);
        const float hb = __shfl_sync(0xffffffffu, hy, k2);
        c0 += ha * W2s[(2 * k2)     * C_OUT + lane];
        c0 += hb * W2s[(2 * k2 + 1) * C_OUT + lane];
        if (lane < 8) {
            c1 += ha * W2s[(2 * k2)     * C_OUT + 32 + lane];
            c1 += hb * W2s[(2 * k2 + 1) * C_OUT + 32 + lane];
        }
    }
    const float t0 = c0 * dd;          // col lane (0..31)
    const float t1 = c1 * dd;          // col 32+lane (lane<8)

    // pack pairs: word m (lane 0..19) = cols {2m, 2m+1}
    const int m = lane;
    float p0 = __shfl_sync(0xffffffffu, t0, (2 * m) & 31);
    float p1 = __shfl_sync(0xffffffffu, t0, (2 * m + 1) & 31);
    float p2 = __shfl_sync(0xffffffffu, t1, (2 * (m - 16)) & 31);
    float p3 = __shfl_sync(0xffffffffu, t1, (2 * (m - 16) + 1) & 31);
    float lo = (m < 16) ? p0 : p2;
    float hi = (m < 16) ? p1 : p3;
    if (lane < 20) g_t2[(size_t)d * 20 + lane] = packbf(lo, hi);
}

// ---------- fused layer-2 aggregate + bias + relu + log_softmax: warp per node ----------
__global__ void __launch_bounds__(256)
k_l2(float* __restrict__ out, const float* __restrict__ b2, int n) {
    __shared__ float b2s[C_OUT];
    const int tid = threadIdx.x;
    if (tid < C_OUT) b2s[tid] = b2[tid];
    __syncthreads();

    const int lane = tid & 31;
    const int d = blockIdx.x * 8 + (tid >> 5);
    if (d >= n) return;

    const int beg = g_row[d];
    const int end = g_row[d + 1];
    const bool act = (lane < 20);

    float ax0 = 0.f, ay0 = 0.f, ax1 = 0.f, ay1 = 0.f;
    float ax2 = 0.f, ay2 = 0.f, ax3 = 0.f, ay3 = 0.f;
    if (act) {
        uint32_t su = g_t2[(size_t)d * 20 + lane];
        ax0 = bflo(su); ay0 = bfhi(su);
    }

    int i = beg;
    for (; i + 8 <= end; i += 8) {
        int s[8];
        #pragma unroll
        for (int j = 0; j < 8; j++) s[j] = g_adj[i + j];
        if (act) {
            uint32_t u[8];
            #pragma unroll
            for (int j = 0; j < 8; j++) u[j] = g_t2[(size_t)s[j] * 20 + lane];
            ax0 += bflo(u[0]); ay0 += bfhi(u[0]);  ax1 += bflo(u[1]); ay1 += bfhi(u[1]);
            ax2 += bflo(u[2]); ay2 += bfhi(u[2]);  ax3 += bflo(u[3]); ay3 += bfhi(u[3]);
            ax0 += bflo(u[4]); ay0 += bfhi(u[4]);  ax1 += bflo(u[5]); ay1 += bfhi(u[5]);
            ax2 += bflo(u[6]); ay2 += bfhi(u[6]);  ax3 += bflo(u[7]); ay3 += bfhi(u[7]);
        }
    }
    for (; i < end; i++) {
        int s = g_adj[i];
        if (act) {
            uint32_t u = g_t2[(size_t)s * 20 + lane];
            ax0 += bflo(u); ay0 += bfhi(u);
        }
    }
    ax0 += ax1 + ax2 + ax3;
    ay0 += ay1 + ay2 + ay3;

    const float dd = g_dinv[d];
    const float v0 = act ? fmaxf(ax0 * dd + b2s[2 * lane],     0.0f) : -1e30f;
    const float v1 = act ? fmaxf(ay0 * dd + b2s[2 * lane + 1], 0.0f) : -1e30f;

    float m = fmaxf(v0, v1);
    #pragma unroll
    for (int o = 16; o; o >>= 1) m = fmaxf(m, __shfl_xor_sync(0xffffffffu, m, o));
    float s = act ? (expf(v0 - m) + expf(v1 - m)) : 0.0f;
    #pragma unroll
    for (int o = 16; o; o >>= 1) s += __shfl_xor_sync(0xffffffffu, s, o);
    const float lse = m + logf(s);

    if (act) {
        float2 r = make_float2(v0 - lse, v1 - lse);
        *(float2*)&out[(size_t)d * C_OUT + 2 * lane] = r;
    }
}

extern "C" void kernel_launch(void* const* d_in, const int* in_sizes, int n_in,
                              void* d_out, int out_size) {
    const float* x  = (const float*)d_in[0];
    const void*  ei = d_in[1];
    const float* W1 = (const float*)d_in[2];
    const float* b1 = (const float*)d_in[3];
    const float* W2 = (const float*)d_in[4];
    const float* b2 = (const float*)d_in[5];
    float*       out = (float*)d_out;

    const int n = in_sizes[0] / F_IN;
    const int E = in_sizes[1] / 2;
    const int nb = (n + 1023) / 1024;

    k_detect      <<<1, 256>>>(ei, E, n);                 // launch 1
    k_zero        <<<(n + 255) / 256, 256>>>(n);          // launch 2
    k_convert_hist<<<(E + 255) / 256, 256>>>(ei, E);      // launch 3

    const int smem = (WROWS * WSTR + GW * 2 * 16 * XSTR) * (int)sizeof(float); // 221184 B
    cudaFuncSetAttribute(k_gemm1, cudaFuncAttributeMaxDynamicSharedMemorySize, smem);
    k_gemm1<<<(n + BM - 1) / BM, GT, smem>>>(x, W1, n);   // launch 4 (profiled)

    k_scanA <<<nb, 1024>>>(n);
    k_scanB <<<1, NBMAX>>>(nb);
    k_scanC <<<(n + 255) / 256, 256>>>(n, E);
    k_fill  <<<(E + 255) / 256, 256>>>(E);

    k_l1<<<(n + 7) / 8, 256>>>(b1, W2, n);
    k_l2<<<(n + 7) / 8, 256>>>(out, b2, n);
}

// round 15
// speedup vs baseline: 1.1827x; 1.0456x over previous
#include <cuda_runtime.h>
#include <cuda_bf16.h>
#include <cstdint>

typedef unsigned long long ull;

#define NMAX   100000
#define EMAX   2000000
#define F_IN   500
#define H1     64
#define C_OUT  40
#define BM     256            // rows per CTA tile (16 warps x 16 rows)
#define GW     16             // warps
#define GT     512            // threads
#define KC     32             // k per chunk
#define NCHUNK 16             // 16*32 = 512 >= 500 (zero-padded)
#define WROWS  512
#define XSTR   36             // x smem row stride (floats)
#define WSTR   72             // W smem row stride (floats)
#define NBMAX  128

// Scratch (allocation-free rule: __device__ globals)
__device__ int      g_degi[NMAX];
__device__ float    g_dinv[NMAX];
__device__ uint32_t g_h1 [(size_t)NMAX * 32];   // bf16x2: cols {2j,2j+1} in word j
__device__ uint32_t g_t2 [(size_t)NMAX * 20];   // bf16x2: cols {2j,2j+1} in word j
__device__ int      g_src [EMAX];
__device__ int      g_dst [EMAX];
__device__ int      g_adj [EMAX];
__device__ int      g_row [NMAX + 1];
__device__ int      g_cur [NMAX];
__device__ int      g_bsum[NBMAX];
__device__ int      g_boff[NBMAX];
__device__ int      g_is64;

// ---------- helpers ----------
__device__ __forceinline__ float to_tf32(float f) {
    float r;
    asm("cvt.rna.tf32.f32 %0, %1;" : "=f"(r) : "f"(f));
    return r;
}
__device__ __forceinline__ void mma_tf32(
    float& d0, float& d1, float& d2, float& d3,
    uint32_t a0, uint32_t a1, uint32_t a2, uint32_t a3,
    uint32_t b0, uint32_t b1) {
    asm volatile(
        "mma.sync.aligned.m16n8k8.row.col.f32.tf32.tf32.f32 "
        "{%0,%1,%2,%3}, {%4,%5,%6,%7}, {%8,%9}, {%0,%1,%2,%3};"
        : "+f"(d0), "+f"(d1), "+f"(d2), "+f"(d3)
        : "r"(a0), "r"(a1), "r"(a2), "r"(a3), "r"(b0), "r"(b1));
}
__device__ __forceinline__ uint32_t smem_u32(const void* p) {
    return (uint32_t)__cvta_generic_to_shared(p);
}
__device__ __forceinline__ void cp16(uint32_t dst, const void* src, int srcsize) {
    asm volatile("cp.async.cg.shared.global [%0], [%1], 16, %2;"
                 :: "r"(dst), "l"(src), "r"(srcsize) : "memory");
}
__device__ __forceinline__ uint32_t packbf(float lo, float hi) {
    __nv_bfloat162 h = __floats2bfloat162_rn(lo, hi);   // .x = lo (low 16 bits)
    return *(uint32_t*)&h;
}
__device__ __forceinline__ float bflo(uint32_t u) { return __uint_as_float(u << 16); }
__device__ __forceinline__ float bfhi(uint32_t u) { return __uint_as_float(u & 0xFFFF0000u); }
__device__ __forceinline__ ull pack2(float lo, float hi) {
    ull r;
    asm("mov.b64 %0, {%1, %2};" : "=l"(r) : "f"(lo), "f"(hi));
    return r;
}
__device__ __forceinline__ void ffma2(ull& d, ull a, ull b) {
    asm("fma.rn.f32x2 %0, %1, %2, %0;" : "+l"(d) : "l"(a), "l"(b));
}

// ---------- edge dtype detection ----------
__global__ void k_detect(const void* __restrict__ ei, int E, int n) {
    const long long* p = (const long long*)ei;
    int m = min(4096, E);
    int bad = 0;
    for (int i = threadIdx.x; i < m; i += blockDim.x) {
        long long v = p[i];
        if (v < 0 || v >= (long long)n) bad = 1;
    }
    bad = __syncthreads_or(bad);
    if (threadIdx.x == 0) g_is64 = bad ? 0 : 1;
}

__global__ void k_zero(int n) {
    int i = blockIdx.x * blockDim.x + threadIdx.x;
    if (i < n) g_degi[i] = 0;
}

// ---------- fused: edge int32 conversion + degree histogram ----------
__global__ void k_convert_hist(const void* __restrict__ ei, int E) {
    int i = blockIdx.x * blockDim.x + threadIdx.x;
    if (i >= E) return;
    int s, d;
    if (g_is64) {
        const long long* p = (const long long*)ei;
        s = (int)p[i];
        d = (int)p[E + i];
    } else {
        const int* p = (const int*)ei;
        s = p[i];
        d = p[E + i];
    }
    g_src[i] = s;
    g_dst[i] = d;
    atomicAdd(&g_degi[d], 1);
}

// ---------- GEMM1 (4th kernel -> profiled): h1 = bf16( dinv * (x @ W1) ) ----------
// R12 structure verbatim: W resident (one barrier), per-warp 2-deep cp.async.
__global__ void __launch_bounds__(GT)
k_gemm1(const float* __restrict__ x, const float* __restrict__ W, int n) {
    extern __shared__ float sm[];
    float* ws = sm;                         // [512][WSTR]
    float* xs = sm + WROWS * WSTR;          // [GW][2][16][XSTR]

    const int tid  = threadIdx.x;
    const int lane = tid & 31;
    const int w    = tid >> 5;
    const int tr   = lane >> 2;
    const int tc   = lane & 3;
    const int row0 = blockIdx.x * BM;
    const int wr   = w * 16;

    float* xw = xs + w * (2 * 16 * XSTR);
    const uint32_t xw_u32 = smem_u32(xw);

    const int lrow  = lane >> 1;
    const int lhalf = lane & 1;
    const int grow  = row0 + wr + lrow;
    const bool rok  = (grow < n);
    const float* gbase = x + (size_t)(rok ? grow : 0) * F_IN;

    #define ISSUE(cc, bb)                                                       \
    {                                                                           \
        _Pragma("unroll")                                                       \
        for (int q = 0; q < 4; q++) {                                           \
            const int f4 = lhalf * 4 + q;                                       \
            const int kg = (cc) * KC + f4 * 4;                                  \
            const int ok = (rok && (kg + 4 <= F_IN)) ? 16 : 0;                  \
            const uint32_t dst = xw_u32 +                                       \
                (uint32_t)(((bb) * 16 + lrow) * XSTR + f4 * 4) * 4u;            \
            cp16(dst, gbase + kg, ok);                                          \
        }                                                                       \
        asm volatile("cp.async.commit_group;" ::: "memory");                    \
    }

    ISSUE(0, 0)
    ISSUE(1, 1)

    const float4* __restrict__ W4 = (const float4*)W;
    #pragma unroll 1
    for (int i = tid; i < WROWS * (H1 / 4); i += GT) {
        const int k = i >> 4, q = i & 15;
        float4 v = make_float4(0.f, 0.f, 0.f, 0.f);
        if (k < F_IN) v = W4[(size_t)k * (H1 / 4) + q];
        v.x = to_tf32(v.x); v.y = to_tf32(v.y);
        v.z = to_tf32(v.z); v.w = to_tf32(v.w);
        *(float4*)&ws[k * WSTR + 4 * q] = v;
    }
    __syncthreads();   // only CTA barrier

    float d[8][4];
    #pragma unroll
    for (int j = 0; j < 8; j++)
        #pragma unroll
        for (int q = 0; q < 4; q++) d[j][q] = 0.0f;

    for (int c = 0; c < NCHUNK; c++) {
        asm volatile("cp.async.wait_group 1;" ::: "memory");
        __syncwarp();

        const int buf = c & 1;
        const float* xb = xw + buf * (16 * XSTR);
        const uint32_t* xa_lo = (const uint32_t*)(xb + tr * XSTR + tc);
        const uint32_t* xa_hi = (const uint32_t*)(xb + (tr + 8) * XSTR + tc);
        const uint32_t* wb0 = (const uint32_t*)(ws + (c * KC + tc) * WSTR + tr);
        const uint32_t* wb1 = (const uint32_t*)(ws + (c * KC + tc + 4) * WSTR + tr);

        #pragma unroll
        for (int s = 0; s < KC / 8; s++) {
            const int kk = 8 * s;
            const uint32_t a0 = xa_lo[kk];
            const uint32_t a1 = xa_hi[kk];
            const uint32_t a2 = xa_lo[kk + 4];
            const uint32_t a3 = xa_hi[kk + 4];
            #pragma unroll
            for (int j = 0; j < 8; j++) {
                const uint32_t b0 = wb0[kk * WSTR + 8 * j];
                const uint32_t b1 = wb1[kk * WSTR + 8 * j];
                mma_tf32(d[j][0], d[j][1], d[j][2], d[j][3], a0, a1, a2, a3, b0, b1);
            }
        }

        if (c + 2 < NCHUNK) {
            ISSUE(c + 2, buf)
        } else {
            asm volatile("cp.async.commit_group;" ::: "memory");
        }
    }
    #undef ISSUE

    // ---- epilogue: dinv scale + bf16 pack + store ----
    const int r_lo = row0 + wr + tr;
    const int r_hi = r_lo + 8;
    if (r_lo < n) {
        const float dd = rsqrtf((float)g_degi[r_lo] + 1.0f);
        if (tc == 0) g_dinv[r_lo] = dd;
        #pragma unroll
        for (int j = 0; j < 8; j++)   // cols 8j+2tc, 8j+2tc+1 -> word 4j+tc
            g_h1[(size_t)r_lo * 32 + 4 * j + tc] = packbf(dd * d[j][0], dd * d[j][1]);
    }
    if (r_hi < n) {
        const float dd = rsqrtf((float)g_degi[r_hi] + 1.0f);
        if (tc == 0) g_dinv[r_hi] = dd;
        #pragma unroll
        for (int j = 0; j < 8; j++)
            g_h1[(size_t)r_hi * 32 + 4 * j + tc] = packbf(dd * d[j][2], dd * d[j][3]);
    }
}

// ---------- CSR build: block scan over degrees ----------
__global__ void __launch_bounds__(1024)
k_scanA(int n) {
    __shared__ int s0[1024], s1[1024];
    const int tid = threadIdx.x;
    const int i = blockIdx.x * 1024 + tid;
    int v = (i < n) ? g_degi[i] : 0;
    s0[tid] = v;
    __syncthreads();
    int* a = s0; int* b = s1;
    #pragma unroll
    for (int off = 1; off < 1024; off <<= 1) {
        b[tid] = a[tid] + ((tid >= off) ? a[tid - off] : 0);
        __syncthreads();
        int* t = a; a = b; b = t;
    }
    if (i < n) g_row[i] = a[tid] - v;
    if (tid == 1023) g_bsum[blockIdx.x] = a[1023];
}
__global__ void __launch_bounds__(NBMAX)
k_scanB(int nb) {
    __shared__ int s0[NBMAX], s1[NBMAX];
    const int tid = threadIdx.x;
    int v = (tid < nb) ? g_bsum[tid] : 0;
    s0[tid] = v;
    __syncthreads();
    int* a = s0; int* b = s1;
    #pragma unroll
    for (int off = 1; off < NBMAX; off <<= 1) {
        b[tid] = a[tid] + ((tid >= off) ? a[tid - off] : 0);
        __syncthreads();
        int* t = a; a = b; b = t;
    }
    if (tid < nb) g_boff[tid] = a[tid] - v;
}
__global__ void k_scanC(int n, int E) {
    int i = blockIdx.x * blockDim.x + threadIdx.x;
    if (i < n) {
        int r = g_row[i] + g_boff[i >> 10];
        g_row[i] = r;
        g_cur[i] = r;
    }
    if (i == 0) g_row[n] = E;
}
__global__ void k_fill(int E) {
    int e = blockIdx.x * blockDim.x + threadIdx.x;
    if (e >= E) return;
    int pos = atomicAdd(&g_cur[g_dst[e]], 1);
    g_adj[pos] = g_src[e];
}

// ---------- fused layer-1 aggregate + bias + relu + GEMM2 (packed FFMA2) ----------
__global__ void __launch_bounds__(256)
k_l1(const float* __restrict__ b1, const float* __restrict__ W2, int n) {
    __shared__ ull   W2p[H1 * 32];   // [k][m]: cols {2m,2m+1}, zero-padded m>=20
    __shared__ float b1s[H1];
    const int tid = threadIdx.x;
    for (int i = tid; i < H1 * 32; i += 256) {
        const int k = i >> 5, m = i & 31;
        W2p[i] = (m < 20) ? pack2(W2[k * C_OUT + 2 * m], W2[k * C_OUT + 2 * m + 1]) : 0ull;
    }
    if (tid < H1) b1s[tid] = b1[tid];
    __syncthreads();

    const int lane = tid & 31;
    const int d = blockIdx.x * 8 + (tid >> 5);
    if (d >= n) return;

    const int beg = g_row[d];
    const int end = g_row[d + 1];

    // self-loop term (bf16x2 word = cols {2*lane, 2*lane+1})
    uint32_t su = g_h1[(size_t)d * 32 + lane];
    float ax0 = bflo(su), ay0 = bfhi(su);
    float ax1 = 0.f, ay1 = 0.f, ax2 = 0.f, ay2 = 0.f, ax3 = 0.f, ay3 = 0.f;

    int i = beg;
    for (; i + 8 <= end; i += 8) {
        int s[8];
        #pragma unroll
        for (int j = 0; j < 8; j++) s[j] = g_adj[i + j];
        uint32_t u[8];
        #pragma unroll
        for (int j = 0; j < 8; j++) u[j] = g_h1[(size_t)s[j] * 32 + lane];
        ax0 += bflo(u[0]); ay0 += bfhi(u[0]);  ax1 += bflo(u[1]); ay1 += bfhi(u[1]);
        ax2 += bflo(u[2]); ay2 += bfhi(u[2]);  ax3 += bflo(u[3]); ay3 += bfhi(u[3]);
        ax0 += bflo(u[4]); ay0 += bfhi(u[4]);  ax1 += bflo(u[5]); ay1 += bfhi(u[5]);
        ax2 += bflo(u[6]); ay2 += bfhi(u[6]);  ax3 += bflo(u[7]); ay3 += bfhi(u[7]);
    }
    for (; i < end; i++) {
        uint32_t u = g_h1[(size_t)g_adj[i] * 32 + lane];
        ax0 += bflo(u); ay0 += bfhi(u);
    }
    ax0 += ax1 + ax2 + ax3;
    ay0 += ay1 + ay2 + ay3;

    const float dd = g_dinv[d];
    const float hx = fmaxf(ax0 * dd + b1s[2 * lane],     0.0f);   // h col 2*lane
    const float hy = fmaxf(ay0 * dd + b1s[2 * lane + 1], 0.0f);   // h col 2*lane+1

    // GEMM2 via packed FFMA2: lane m accumulates output cols {2m, 2m+1}
    ull acc = 0ull;
    #pragma unroll
    for (int k2 = 0; k2 < 32; k2++) {
        const float ha = __shfl_sync(0xffffffffu, hx, k2);   // h[2*k2]
        const float hb = __shfl_sync(0xffffffffu, hy, k2);   // h[2*k2+1]
        ffma2(acc, pack2(ha, ha), W2p[(2 * k2) * 32 + lane]);
        ffma2(acc, pack2(hb, hb), W2p[(2 * k2 + 1) * 32 + lane]);
    }
    float2 r = *(float2*)&acc;
    if (lane < 20) g_t2[(size_t)d * 20 + lane] = packbf(r.x * dd, r.y * dd);
}

// ---------- fused layer-2 aggregate + bias + relu + log_softmax: warp per node ----------
__global__ void __launch_bounds__(256)
k_l2(float* __restrict__ out, const float* __restrict__ b2, int n) {
    __shared__ float b2s[C_OUT];
    const int tid = threadIdx.x;
    if (tid < C_OUT) b2s[tid] = b2[tid];
    __syncthreads();

    const int lane = tid & 31;
    const int d = blockIdx.x * 8 + (tid >> 5);
    if (d >= n) return;

    const int beg = g_row[d];
    const int end = g_row[d + 1];
    const bool act = (lane < 20);

    float ax0 = 0.f, ay0 = 0.f, ax1 = 0.f, ay1 = 0.f;
    float ax2 = 0.f, ay2 = 0.f, ax3 = 0.f, ay3 = 0.f;
    if (act) {
        uint32_t su = g_t2[(size_t)d * 20 + lane];
        ax0 = bflo(su); ay0 = bfhi(su);
    }

    int i = beg;
    for (; i + 8 <= end; i += 8) {
        int s[8];
        #pragma unroll
        for (int j = 0; j < 8; j++) s[j] = g_adj[i + j];
        if (act) {
            uint32_t u[8];
            #pragma unroll
            for (int j = 0; j < 8; j++) u[j] = g_t2[(size_t)s[j] * 20 + lane];
            ax0 += bflo(u[0]); ay0 += bfhi(u[0]);  ax1 += bflo(u[1]); ay1 += bfhi(u[1]);
            ax2 += bflo(u[2]); ay2 += bfhi(u[2]);  ax3 += bflo(u[3]); ay3 += bfhi(u[3]);
            ax0 += bflo(u[4]); ay0 += bfhi(u[4]);  ax1 += bflo(u[5]); ay1 += bfhi(u[5]);
            ax2 += bflo(u[6]); ay2 += bfhi(u[6]);  ax3 += bflo(u[7]); ay3 += bfhi(u[7]);
        }
    }
    for (; i < end; i++) {
        int s = g_adj[i];
        if (act) {
            uint32_t u = g_t2[(size_t)s * 20 + lane];
            ax0 += bflo(u); ay0 += bfhi(u);
        }
    }
    ax0 += ax1 + ax2 + ax3;
    ay0 += ay1 + ay2 + ay3;

    const float dd = g_dinv[d];
    const float v0 = act ? fmaxf(ax0 * dd + b2s[2 * lane],     0.0f) : -1e30f;
    const float v1 = act ? fmaxf(ay0 * dd + b2s[2 * lane + 1], 0.0f) : -1e30f;

    float m = fmaxf(v0, v1);
    #pragma unroll
    for (int o = 16; o; o >>= 1) m = fmaxf(m, __shfl_xor_sync(0xffffffffu, m, o));
    float s = act ? (expf(v0 - m) + expf(v1 - m)) : 0.0f;
    #pragma unroll
    for (int o = 16; o; o >>= 1) s += __shfl_xor_sync(0xffffffffu, s, o);
    const float lse = m + logf(s);

    if (act) {
        float2 r = make_float2(v0 - lse, v1 - lse);
        *(float2*)&out[(size_t)d * C_OUT + 2 * lane] = r;
    }
}

extern "C" void kernel_launch(void* const* d_in, const int* in_sizes, int n_in,
                              void* d_out, int out_size) {
    const float* x  = (const float*)d_in[0];
    const void*  ei = d_in[1];
    const float* W1 = (const float*)d_in[2];
    const float* b1 = (const float*)d_in[3];
    const float* W2 = (const float*)d_in[4];
    const float* b2 = (const float*)d_in[5];
    float*       out = (float*)d_out;

    const int n = in_sizes[0] / F_IN;
    const int E = in_sizes[1] / 2;
    const int nb = (n + 1023) / 1024;

    // Side stream + events for CSR-build / GEMM1 overlap. Created once,
    // reused on every call (the captured graph is identical each time).
    static cudaStream_t s2 = nullptr;
    static cudaEvent_t ev1 = nullptr, ev2 = nullptr;
    if (s2 == nullptr) {
        cudaStreamCreateWithFlags(&s2, cudaStreamNonBlocking);
        cudaEventCreateWithFlags(&ev1, cudaEventDisableTiming);
        cudaEventCreateWithFlags(&ev2, cudaEventDisableTiming);
    }

    k_detect      <<<1, 256>>>(ei, E, n);                 // kernel 1
    k_zero        <<<(n + 255) / 256, 256>>>(n);          // kernel 2
    k_convert_hist<<<(E + 255) / 256, 256>>>(ei, E);      // kernel 3

    cudaEventRecord(ev1, 0);                              // hist done

    const int smem = (WROWS * WSTR + GW * 2 * 16 * XSTR) * (int)sizeof(float); // 221184 B
    cudaFuncSetAttribute(k_gemm1, cudaFuncAttributeMaxDynamicSharedMemorySize, smem);
    k_gemm1<<<(n + BM - 1) / BM, GT, smem>>>(x, W1, n);   // kernel 4 (profiled)

    // CSR build overlaps gemm1 on side stream
    cudaStreamWaitEvent(s2, ev1, 0);
    k_scanA <<<nb, 1024, 0, s2>>>(n);
    k_scanB <<<1, NBMAX, 0, s2>>>(nb);
    k_scanC <<<(n + 255) / 256, 256, 0, s2>>>(n, E);
    k_fill  <<<(E + 255) / 256, 256, 0, s2>>>(E);
    cudaEventRecord(ev2, s2);
    cudaStreamWaitEvent(0, ev2, 0);                       // join before l1

    k_l1<<<(n + 7) / 8, 256>>>(b1, W2, n);
    k_l2<<<(n + 7) / 8, 256>>>(out, b2, n);
}